// round 16
// baseline (speedup 1.0000x reference)
#include <cuda_runtime.h>
#include <cuda_fp16.h>
#include <cstdint>
#include <math.h>

#define BB 128
#define DD 512
#define TT 1024
#define GG 256
#define KK 32
#define HH 64
#define CC 4
#define QB 32          // batches per quarter
#define NQ 4
#define SCALE 0.17677669529663687f   // 1/sqrt(32)

// Scratch (allocation-free rule: __device__ globals)
__device__ float g_u[BB*DD];
__device__ float g_c[BB*DD];
__device__ float g_Sc[BB];
__device__ float g_Scc[BB];
__device__ float g_sc[BB*TT];
__device__ float g_s1[BB*TT];
__device__ float g_s2[BB*TT];
__device__ float g_sx[BB*TT];
__device__ float g_R1[BB];
__device__ float g_R2[BB];
__device__ float g_A[BB*DD];
// fp16 stash of the current quarter's x, reused every quarter (32 MB).
__device__ __half g_xh[(size_t)QB*DD*TT];

__device__ __forceinline__ float warpSum(float v) {
    #pragma unroll
    for (int o = 16; o > 0; o >>= 1) v += __shfl_xor_sync(0xffffffffu, v, o);
    return v;
}
__device__ __forceinline__ float warpMax(float v) {
    #pragma unroll
    for (int o = 16; o > 0; o >>= 1) v = fmaxf(v, __shfl_xor_sync(0xffffffffu, v, o));
    return v;
}

// ---------------------------------------------------------------------------
// k1: per-batch precompute (KV -> u, c, Sc, Scc). One block (256 thr) per b.
// ---------------------------------------------------------------------------
__global__ void __launch_bounds__(256) k1_prep(
        const float* __restrict__ gaf, const float* __restrict__ Wq,
        const float* __restrict__ Wkv, const float* __restrict__ Wout) {
    int b = blockIdx.x, tid = threadIdx.x, w = tid >> 5, lane = tid & 31;
    __shared__ float s_gaf[GG];
    __shared__ float s_kv[KK];
    __shared__ float red[16];

    s_gaf[tid] = gaf[b * GG + tid];
    __syncthreads();

    #pragma unroll
    for (int kk = 0; kk < 4; kk++) {
        int k = w * 4 + kk;
        float acc = 0.f;
        #pragma unroll
        for (int i = 0; i < 8; i++)
            acc += s_gaf[lane + 32 * i] * Wkv[k * GG + lane + 32 * i];
        acc = warpSum(acc);
        if (lane == 0) s_kv[k] = acc;
    }
    __syncthreads();

    float lsc = 0.f, lscc = 0.f;
    #pragma unroll
    for (int it = 0; it < 2; it++) {
        int d = tid + it * 256;
        float uu = 0.f;
        #pragma unroll
        for (int k = 0; k < KK; k++) uu += Wq[k * DD + d] * s_kv[k];
        float cc = 0.f;
        const float4* wo = (const float4*)(Wout + d * KK);
        #pragma unroll
        for (int qq = 0; qq < 8; qq++) {
            float4 v = wo[qq];
            cc += v.x*s_kv[qq*4] + v.y*s_kv[qq*4+1] + v.z*s_kv[qq*4+2] + v.w*s_kv[qq*4+3];
        }
        g_u[b * DD + d] = uu;
        g_c[b * DD + d] = cc;
        lsc += cc; lscc += cc * cc;
    }
    lsc = warpSum(lsc); lscc = warpSum(lscc);
    if (lane == 0) { red[w] = lsc; red[8 + w] = lscc; }
    __syncthreads();
    if (tid == 0) {
        float a = 0.f, s = 0.f;
        #pragma unroll
        for (int i = 0; i < 8; i++) { a += red[i]; s += red[8 + i]; }
        g_Sc[b] = a; g_Scc[b] = s;
    }
}

// ---------------------------------------------------------------------------
// k2(q): stats pass + fp16 stash write. Block = (ts 0..7, bq). 128 t x 512 d.
// ---------------------------------------------------------------------------
__global__ void __launch_bounds__(256) k2_stats(const float* __restrict__ tcf, int q) {
    int ts = blockIdx.x, bl = blockIdx.y, b = q * QB + bl;
    int tid = threadIdx.x, dg = tid >> 5, lane = tid & 31;
    __shared__ float s_u[DD], s_c[DD];
    __shared__ float red[8 * 32 * 16];   // 16 KB

    #pragma unroll
    for (int it = 0; it < 2; it++) {
        int d = tid + it * 256;
        s_u[d] = g_u[b * DD + d];
        s_c[d] = g_c[b * DD + d];
    }
    __syncthreads();

    const float4* xp = (const float4*)(tcf + ((size_t)b * DD + dg * 64) * TT + ts * 128) + lane;
    uint2* xh = (uint2*)(g_xh + ((size_t)bl * DD + dg * 64) * TT + ts * 128) + lane;
    float4 dot = {0,0,0,0}, s1 = {0,0,0,0}, s2 = {0,0,0,0}, sx = {0,0,0,0};

    #pragma unroll 16
    for (int r = 0; r < 64; r++) {
        float4 xv = xp[(size_t)r * 256];
        float uu = s_u[dg * 64 + r];
        float cc = s_c[dg * 64 + r];
        dot.x += xv.x*uu; dot.y += xv.y*uu; dot.z += xv.z*uu; dot.w += xv.w*uu;
        s1.x  += xv.x;    s1.y  += xv.y;    s1.z  += xv.z;    s1.w  += xv.w;
        s2.x  += xv.x*xv.x; s2.y += xv.y*xv.y; s2.z += xv.z*xv.z; s2.w += xv.w*xv.w;
        sx.x  += xv.x*cc; sx.y  += xv.y*cc; sx.z  += xv.z*cc; sx.w  += xv.w*cc;
        // fp16 stash (consumed by k4 from L2)
        half2 h01 = __floats2half2_rn(xv.x, xv.y);
        half2 h23 = __floats2half2_rn(xv.z, xv.w);
        uint2 pk;
        pk.x = *reinterpret_cast<unsigned int*>(&h01);
        pk.y = *reinterpret_cast<unsigned int*>(&h23);
        xh[(size_t)r * 256] = pk;
    }

    float4* red4 = (float4*)red;
    int base = (dg * 32 + lane) * 4;
    red4[base + 0] = dot;
    red4[base + 1] = s1;
    red4[base + 2] = s2;
    red4[base + 3] = sx;
    __syncthreads();

    if (tid < 128) {
        int lo = tid >> 2, comp = tid & 3;
        float a0 = 0.f, a1 = 0.f, a2 = 0.f, a3 = 0.f;
        #pragma unroll
        for (int g2 = 0; g2 < 8; g2++) {
            int bx = ((g2 * 32 + lo) * 4) * 4 + comp;
            a0 += red[bx];
            a1 += red[bx + 4];
            a2 += red[bx + 8];
            a3 += red[bx + 12];
        }
        int idx = b * TT + ts * 128 + tid;
        g_sc[idx] = a0 * SCALE;
        g_s1[idx] = a1;
        g_s2[idx] = a2;
        g_sx[idx] = a3;
    }
}

// ---------------------------------------------------------------------------
// k4(q): softmax+rstd prologue (redundant per block), then A[b,d] over own
// 64 d rows reading the fp16 stash (L2-hot). Block = (ch 0..7, bq).
// ---------------------------------------------------------------------------
__global__ void __launch_bounds__(256) k4_A(int q) {
    int ch = blockIdx.x, bl = blockIdx.y, b = q * QB + bl;
    int tid = threadIdx.x, w = tid >> 5, lane = tid & 31;
    __shared__ float s_r[TT];      // rstd, 4 KB
    __shared__ float red[8], redb[8];
    __shared__ float bval;

    // ---- Prologue: per-batch softmax + rstd (identical in all 8 ch-blocks).
    float4 sc4 = ((const float4*)(g_sc + b * TT))[tid];
    float m = fmaxf(fmaxf(sc4.x, sc4.y), fmaxf(sc4.z, sc4.w));
    m = warpMax(m);
    if (lane == 0) red[w] = m;
    __syncthreads();
    if (tid == 0) {
        float mm = red[0];
        #pragma unroll
        for (int i = 1; i < 8; i++) mm = fmaxf(mm, red[i]);
        bval = mm;
    }
    __syncthreads();
    m = bval;

    float ee[4];
    ee[0] = expf(sc4.x - m); ee[1] = expf(sc4.y - m);
    ee[2] = expf(sc4.z - m); ee[3] = expf(sc4.w - m);
    float se = warpSum(ee[0] + ee[1] + ee[2] + ee[3]);
    __syncthreads();
    if (lane == 0) red[w] = se;
    __syncthreads();
    if (tid == 0) {
        float s = 0.f;
        #pragma unroll
        for (int i = 0; i < 8; i++) s += red[i];
        bval = s;
    }
    __syncthreads();
    float inv = 1.f / bval;

    float Scb = g_Sc[b], Sccb = g_Scc[b];
    float4 v1 = ((const float4*)(g_s1 + b * TT))[tid];
    float4 v2 = ((const float4*)(g_s2 + b * TT))[tid];
    float4 vx = ((const float4*)(g_sx + b * TT))[tid];
    float vs1[4] = {v1.x, v1.y, v1.z, v1.w};
    float vs2[4] = {v2.x, v2.y, v2.z, v2.w};
    float vsx[4] = {vx.x, vx.y, vx.z, vx.w};

    float r1 = 0.f, r2 = 0.f, rs[4];
    #pragma unroll
    for (int i = 0; i < 4; i++) {
        float wgt = ee[i] * inv;
        float mu = (vs1[i] + wgt * Scb) * (1.f / DD);
        float ms = (vs2[i] + 2.f * wgt * vsx[i] + wgt * wgt * Sccb) * (1.f / DD);
        rs[i] = rsqrtf(ms - mu * mu + 1e-5f);
        r1 += rs[i] * wgt;
        r2 += rs[i] * mu;
    }
    *(float4*)(s_r + tid * 4) = make_float4(rs[0], rs[1], rs[2], rs[3]);

    if (ch == 0) {
        r1 = warpSum(r1); r2 = warpSum(r2);
        if (lane == 0) { red[w] = r1; redb[w] = r2; }
    }
    __syncthreads();
    if (ch == 0 && tid == 0) {
        float a = 0.f, c = 0.f;
        #pragma unroll
        for (int i = 0; i < 8; i++) { a += red[i]; c += redb[i]; }
        g_R1[b] = a; g_R2[b] = c;
    }

    // ---- Main: A over own 64 d rows, x from fp16 stash (L2).
    #pragma unroll
    for (int rr = 0; rr < 8; rr++) {
        int d = ch * 64 + w * 8 + rr;
        const uint2* xr = (const uint2*)(g_xh + ((size_t)bl * DD + d) * TT);
        float acc = 0.f;
        #pragma unroll
        for (int j = 0; j < 8; j++) {
            uint2 pk = xr[lane + j * 32];
            half2 h01 = *reinterpret_cast<half2*>(&pk.x);
            half2 h23 = *reinterpret_cast<half2*>(&pk.y);
            float2 f01 = __half22float2(h01);
            float2 f23 = __half22float2(h23);
            float4 rv = *(const float4*)(s_r + (lane + j * 32) * 4);
            acc += f01.x*rv.x + f01.y*rv.y + f23.x*rv.z + f23.y*rv.w;
        }
        acc = warpSum(acc);
        if (lane == 0) g_A[b * DD + d] = acc;
    }
}

// ---------------------------------------------------------------------------
// k5: pooled + MLP head + output. ILP-heavy matvec.
// ---------------------------------------------------------------------------
__global__ void __launch_bounds__(256) k5_head(
        const float* __restrict__ ln1g, const float* __restrict__ ln1b,
        const float* __restrict__ W1, const float* __restrict__ b1,
        const float* __restrict__ ln2g, const float* __restrict__ ln2b,
        const float* __restrict__ W2, const float* __restrict__ b2,
        float* __restrict__ out) {
    int b = blockIdx.x, tid = threadIdx.x;
    int w = tid >> 5, lane = tid & 31;
    __shared__ float pooled[DD];
    __shared__ float t1[HH];
    __shared__ float act[HH];
    __shared__ float smu, srstd;

    float R1 = g_R1[b], R2 = g_R2[b];
    #pragma unroll
    for (int it = 0; it < 2; it++) {
        int d = tid + it * 256;
        pooled[d] = ln1g[d] * ((g_A[b * DD + d] + g_c[b * DD + d] * R1 - R2) * (1.f / TT)) + ln1b[d];
    }
    __syncthreads();

    float acc[8] = {0,0,0,0,0,0,0,0};
    #pragma unroll
    for (int i = 0; i < 16; i++) {
        float pd = pooled[lane + 32 * i];
        #pragma unroll
        for (int hh = 0; hh < 8; hh++)
            acc[hh] += pd * W1[(w * 8 + hh) * DD + lane + 32 * i];
    }
    #pragma unroll
    for (int hh = 0; hh < 8; hh++) {
        float a = warpSum(acc[hh]);
        if (lane == 0) t1[w * 8 + hh] = a + b1[w * 8 + hh];
    }
    __syncthreads();

    if (w == 0) {
        float a = t1[lane], bb = t1[lane + 32];
        float sum = warpSum(a + bb) * (1.f / HH);
        float sq  = warpSum(a * a + bb * bb) * (1.f / HH);
        if (lane == 0) { smu = sum; srstd = rsqrtf(sq - sum * sum + 1e-5f); }
    }
    __syncthreads();

    if (tid < HH) {
        float v = (t1[tid] - smu) * srstd * ln2g[tid] + ln2b[tid];
        act[tid] = v > 0.f ? v : (expf(v) - 1.f);
    }
    __syncthreads();

    if (w < CC) {
        float acc2 = act[lane] * W2[w * HH + lane] + act[lane + 32] * W2[w * HH + lane + 32];
        acc2 = warpSum(acc2);
        if (lane == 0) out[b * CC + w] = acc2 + b2[w];
    }
}

extern "C" void kernel_launch(void* const* d_in, const int* in_sizes, int n_in,
                              void* d_out, int out_size) {
    const float* tcf  = (const float*)d_in[0];
    const float* gaf  = (const float*)d_in[1];
    const float* Wq   = (const float*)d_in[2];
    const float* Wkv  = (const float*)d_in[3];
    const float* Wout = (const float*)d_in[4];
    const float* ln1g = (const float*)d_in[5];
    const float* ln1b = (const float*)d_in[6];
    const float* W1   = (const float*)d_in[7];
    const float* b1   = (const float*)d_in[8];
    const float* ln2g = (const float*)d_in[9];
    const float* ln2b = (const float*)d_in[10];
    const float* W2   = (const float*)d_in[11];
    const float* b2   = (const float*)d_in[12];
    float* out = (float*)d_out;

    k1_prep<<<BB, 256>>>(gaf, Wq, Wkv, Wout);
    for (int q = 0; q < NQ; q++) {
        k2_stats<<<dim3(8, QB), 256>>>(tcf, q);
        k4_A<<<dim3(8, QB), 256>>>(q);
    }
    k5_head<<<BB, 256>>>(ln1g, ln1b, W1, b1, ln2g, ln2b, W2, b2, out);
}

// round 17
// speedup vs baseline: 1.1311x; 1.1311x over previous
#include <cuda_runtime.h>
#include <cstdint>
#include <math.h>

#define BB 128
#define DD 512
#define TT 1024
#define GG 256
#define KK 32
#define HH 64
#define CC 4
#define QB 32          // batches per quarter (64 MB -> L2 for k4 re-read)
#define NQ 4
#define SCALE 0.17677669529663687f   // 1/sqrt(32)

// Scratch (allocation-free rule: __device__ globals)
__device__ float g_u[BB*DD];
__device__ float g_c[BB*DD];
__device__ float g_Sc[BB];
__device__ float g_Scc[BB];
// stats split in two d-halves (dp), summed in k4 prologue
__device__ float g_sc[2*BB*TT];
__device__ float g_s1[2*BB*TT];
__device__ float g_s2[2*BB*TT];
__device__ float g_sx[2*BB*TT];
__device__ float g_R1[BB];
__device__ float g_R2[BB];
__device__ float g_A[BB*DD];

__device__ __forceinline__ float warpSum(float v) {
    #pragma unroll
    for (int o = 16; o > 0; o >>= 1) v += __shfl_xor_sync(0xffffffffu, v, o);
    return v;
}
__device__ __forceinline__ float warpMax(float v) {
    #pragma unroll
    for (int o = 16; o > 0; o >>= 1) v = fmaxf(v, __shfl_xor_sync(0xffffffffu, v, o));
    return v;
}

// ---------------------------------------------------------------------------
// k1: per-batch precompute (KV -> u, c, Sc, Scc). One block (256 thr) per b.
// ---------------------------------------------------------------------------
__global__ void __launch_bounds__(256) k1_prep(
        const float* __restrict__ gaf, const float* __restrict__ Wq,
        const float* __restrict__ Wkv, const float* __restrict__ Wout) {
    int b = blockIdx.x, tid = threadIdx.x, w = tid >> 5, lane = tid & 31;
    __shared__ float s_gaf[GG];
    __shared__ float s_kv[KK];
    __shared__ float red[16];

    s_gaf[tid] = gaf[b * GG + tid];
    __syncthreads();

    #pragma unroll
    for (int kk = 0; kk < 4; kk++) {
        int k = w * 4 + kk;
        float acc = 0.f;
        #pragma unroll
        for (int i = 0; i < 8; i++)
            acc += s_gaf[lane + 32 * i] * Wkv[k * GG + lane + 32 * i];
        acc = warpSum(acc);
        if (lane == 0) s_kv[k] = acc;
    }
    __syncthreads();

    float lsc = 0.f, lscc = 0.f;
    #pragma unroll
    for (int it = 0; it < 2; it++) {
        int d = tid + it * 256;
        float uu = 0.f;
        #pragma unroll
        for (int k = 0; k < KK; k++) uu += Wq[k * DD + d] * s_kv[k];
        float cc = 0.f;
        const float4* wo = (const float4*)(Wout + d * KK);
        #pragma unroll
        for (int qq = 0; qq < 8; qq++) {
            float4 v = wo[qq];
            cc += v.x*s_kv[qq*4] + v.y*s_kv[qq*4+1] + v.z*s_kv[qq*4+2] + v.w*s_kv[qq*4+3];
        }
        g_u[b * DD + d] = uu;
        g_c[b * DD + d] = cc;
        lsc += cc; lscc += cc * cc;
    }
    lsc = warpSum(lsc); lscc = warpSum(lscc);
    if (lane == 0) { red[w] = lsc; red[8 + w] = lscc; }
    __syncthreads();
    if (tid == 0) {
        float a = 0.f, s = 0.f;
        #pragma unroll
        for (int i = 0; i < 8; i++) { a += red[i]; s += red[8 + i]; }
        g_Sc[b] = a; g_Scc[b] = s;
    }
}

// ---------------------------------------------------------------------------
// k2(q): stats pass. Block = (ts 0..7, dp 0..1, bq 0..31) = 512 blocks.
// 128 t x 256 d per block; per-dp partial stats summed in k4 prologue.
// ---------------------------------------------------------------------------
__global__ void __launch_bounds__(256) k2_stats(const float* __restrict__ tcf, int q) {
    int ts = blockIdx.x, dp = blockIdx.y, b = q * QB + blockIdx.z;
    int tid = threadIdx.x, dg = tid >> 5, lane = tid & 31;
    __shared__ float s_u[256], s_c[256];
    __shared__ float red[8 * 32 * 16];   // 16 KB

    s_u[tid] = g_u[b * DD + dp * 256 + tid];
    s_c[tid] = g_c[b * DD + dp * 256 + tid];
    __syncthreads();

    const float4* xp = (const float4*)(tcf + ((size_t)b * DD + dp * 256 + dg * 32) * TT + ts * 128) + lane;
    float4 dot = {0,0,0,0}, s1 = {0,0,0,0}, s2 = {0,0,0,0}, sx = {0,0,0,0};

    #pragma unroll 16
    for (int r = 0; r < 32; r++) {
        float4 xv = xp[(size_t)r * 256];
        float uu = s_u[dg * 32 + r];
        float cc = s_c[dg * 32 + r];
        dot.x += xv.x*uu; dot.y += xv.y*uu; dot.z += xv.z*uu; dot.w += xv.w*uu;
        s1.x  += xv.x;    s1.y  += xv.y;    s1.z  += xv.z;    s1.w  += xv.w;
        s2.x  += xv.x*xv.x; s2.y += xv.y*xv.y; s2.z += xv.z*xv.z; s2.w += xv.w*xv.w;
        sx.x  += xv.x*cc; sx.y  += xv.y*cc; sx.z  += xv.z*cc; sx.w  += xv.w*cc;
    }

    float4* red4 = (float4*)red;
    int base = (dg * 32 + lane) * 4;
    red4[base + 0] = dot;
    red4[base + 1] = s1;
    red4[base + 2] = s2;
    red4[base + 3] = sx;
    __syncthreads();

    if (tid < 128) {
        int lo = tid >> 2, comp = tid & 3;
        float a0 = 0.f, a1 = 0.f, a2 = 0.f, a3 = 0.f;
        #pragma unroll
        for (int g2 = 0; g2 < 8; g2++) {
            int bx = ((g2 * 32 + lo) * 4) * 4 + comp;
            a0 += red[bx];
            a1 += red[bx + 4];
            a2 += red[bx + 8];
            a3 += red[bx + 12];
        }
        size_t idx = ((size_t)dp * BB + b) * TT + ts * 128 + tid;
        g_sc[idx] = a0;       // raw dot; SCALE applied in k4
        g_s1[idx] = a1;
        g_s2[idx] = a2;
        g_sx[idx] = a3;
    }
}

// ---------------------------------------------------------------------------
// k4(q): softmax+rstd prologue (sums dp halves; redundant per block), then
// A[b,d] over own 32 d rows, x re-read from L2-hot tcf lines.
// Block = (ch 0..15, bq 0..31) = 512 blocks.
// ---------------------------------------------------------------------------
__global__ void __launch_bounds__(256) k4_A(const float* __restrict__ tcf, int q) {
    int ch = blockIdx.x, b = q * QB + blockIdx.y;
    int tid = threadIdx.x, w = tid >> 5, lane = tid & 31;
    __shared__ float s_r[TT];      // rstd, 4 KB
    __shared__ float red[8], redb[8];
    __shared__ float bval;

    const float4* p0 = (const float4*)(g_sc + (size_t)b * TT) + tid;
    const float4* p1 = (const float4*)(g_sc + ((size_t)BB + b) * TT) + tid;
    float4 a0 = *p0, a1 = *p1;
    float4 sc4 = make_float4((a0.x+a1.x)*SCALE, (a0.y+a1.y)*SCALE,
                             (a0.z+a1.z)*SCALE, (a0.w+a1.w)*SCALE);

    float m = fmaxf(fmaxf(sc4.x, sc4.y), fmaxf(sc4.z, sc4.w));
    m = warpMax(m);
    if (lane == 0) red[w] = m;
    __syncthreads();
    if (tid == 0) {
        float mm = red[0];
        #pragma unroll
        for (int i = 1; i < 8; i++) mm = fmaxf(mm, red[i]);
        bval = mm;
    }
    __syncthreads();
    m = bval;

    float ee[4];
    ee[0] = expf(sc4.x - m); ee[1] = expf(sc4.y - m);
    ee[2] = expf(sc4.z - m); ee[3] = expf(sc4.w - m);
    float se = warpSum(ee[0] + ee[1] + ee[2] + ee[3]);
    __syncthreads();
    if (lane == 0) red[w] = se;
    __syncthreads();
    if (tid == 0) {
        float s = 0.f;
        #pragma unroll
        for (int i = 0; i < 8; i++) s += red[i];
        bval = s;
    }
    __syncthreads();
    float inv = 1.f / bval;

    float Scb = g_Sc[b], Sccb = g_Scc[b];
    float4 v1a = ((const float4*)(g_s1 + (size_t)b * TT))[tid];
    float4 v1b = ((const float4*)(g_s1 + ((size_t)BB + b) * TT))[tid];
    float4 v2a = ((const float4*)(g_s2 + (size_t)b * TT))[tid];
    float4 v2b = ((const float4*)(g_s2 + ((size_t)BB + b) * TT))[tid];
    float4 vxa = ((const float4*)(g_sx + (size_t)b * TT))[tid];
    float4 vxb = ((const float4*)(g_sx + ((size_t)BB + b) * TT))[tid];
    float vs1[4] = {v1a.x+v1b.x, v1a.y+v1b.y, v1a.z+v1b.z, v1a.w+v1b.w};
    float vs2[4] = {v2a.x+v2b.x, v2a.y+v2b.y, v2a.z+v2b.z, v2a.w+v2b.w};
    float vsx[4] = {vxa.x+vxb.x, vxa.y+vxb.y, vxa.z+vxb.z, vxa.w+vxb.w};

    float r1 = 0.f, r2 = 0.f, rs[4];
    #pragma unroll
    for (int i = 0; i < 4; i++) {
        float wgt = ee[i] * inv;
        float mu = (vs1[i] + wgt * Scb) * (1.f / DD);
        float ms = (vs2[i] + 2.f * wgt * vsx[i] + wgt * wgt * Sccb) * (1.f / DD);
        rs[i] = rsqrtf(ms - mu * mu + 1e-5f);
        r1 += rs[i] * wgt;
        r2 += rs[i] * mu;
    }
    *(float4*)(s_r + tid * 4) = make_float4(rs[0], rs[1], rs[2], rs[3]);

    if (ch == 0) {
        r1 = warpSum(r1); r2 = warpSum(r2);
        if (lane == 0) { red[w] = r1; redb[w] = r2; }
    }
    __syncthreads();
    if (ch == 0 && tid == 0) {
        float a = 0.f, c = 0.f;
        #pragma unroll
        for (int i = 0; i < 8; i++) { a += red[i]; c += redb[i]; }
        g_R1[b] = a; g_R2[b] = c;
    }

    // ---- Main: A over own 32 d rows.
    #pragma unroll
    for (int rr = 0; rr < 4; rr++) {
        int d = ch * 32 + w * 4 + rr;
        const float4* xr = (const float4*)(tcf + ((size_t)b * DD + d) * TT);
        float acc = 0.f;
        #pragma unroll
        for (int j = 0; j < 8; j++) {
            float4 xv = xr[lane + j * 32];
            float4 rv = *(const float4*)(s_r + (lane + j * 32) * 4);
            acc += xv.x*rv.x + xv.y*rv.y + xv.z*rv.z + xv.w*rv.w;
        }
        acc = warpSum(acc);
        if (lane == 0) g_A[b * DD + d] = acc;
    }
}

// ---------------------------------------------------------------------------
// k5: pooled + MLP head + output. ILP-heavy matvec.
// ---------------------------------------------------------------------------
__global__ void __launch_bounds__(256) k5_head(
        const float* __restrict__ ln1g, const float* __restrict__ ln1b,
        const float* __restrict__ W1, const float* __restrict__ b1,
        const float* __restrict__ ln2g, const float* __restrict__ ln2b,
        const float* __restrict__ W2, const float* __restrict__ b2,
        float* __restrict__ out) {
    int b = blockIdx.x, tid = threadIdx.x;
    int w = tid >> 5, lane = tid & 31;
    __shared__ float pooled[DD];
    __shared__ float t1[HH];
    __shared__ float act[HH];
    __shared__ float smu, srstd;

    float R1 = g_R1[b], R2 = g_R2[b];
    #pragma unroll
    for (int it = 0; it < 2; it++) {
        int d = tid + it * 256;
        pooled[d] = ln1g[d] * ((g_A[b * DD + d] + g_c[b * DD + d] * R1 - R2) * (1.f / TT)) + ln1b[d];
    }
    __syncthreads();

    float acc[8] = {0,0,0,0,0,0,0,0};
    #pragma unroll
    for (int i = 0; i < 16; i++) {
        float pd = pooled[lane + 32 * i];
        #pragma unroll
        for (int hh = 0; hh < 8; hh++)
            acc[hh] += pd * W1[(w * 8 + hh) * DD + lane + 32 * i];
    }
    #pragma unroll
    for (int hh = 0; hh < 8; hh++) {
        float a = warpSum(acc[hh]);
        if (lane == 0) t1[w * 8 + hh] = a + b1[w * 8 + hh];
    }
    __syncthreads();

    if (w == 0) {
        float a = t1[lane], bb = t1[lane + 32];
        float sum = warpSum(a + bb) * (1.f / HH);
        float sq  = warpSum(a * a + bb * bb) * (1.f / HH);
        if (lane == 0) { smu = sum; srstd = rsqrtf(sq - sum * sum + 1e-5f); }
    }
    __syncthreads();

    if (tid < HH) {
        float v = (t1[tid] - smu) * srstd * ln2g[tid] + ln2b[tid];
        act[tid] = v > 0.f ? v : (expf(v) - 1.f);
    }
    __syncthreads();

    if (w < CC) {
        float acc2 = act[lane] * W2[w * HH + lane] + act[lane + 32] * W2[w * HH + lane + 32];
        acc2 = warpSum(acc2);
        if (lane == 0) out[b * CC + w] = acc2 + b2[w];
    }
}

extern "C" void kernel_launch(void* const* d_in, const int* in_sizes, int n_in,
                              void* d_out, int out_size) {
    const float* tcf  = (const float*)d_in[0];
    const float* gaf  = (const float*)d_in[1];
    const float* Wq   = (const float*)d_in[2];
    const float* Wkv  = (const float*)d_in[3];
    const float* Wout = (const float*)d_in[4];
    const float* ln1g = (const float*)d_in[5];
    const float* ln1b = (const float*)d_in[6];
    const float* W1   = (const float*)d_in[7];
    const float* b1   = (const float*)d_in[8];
    const float* ln2g = (const float*)d_in[9];
    const float* ln2b = (const float*)d_in[10];
    const float* W2   = (const float*)d_in[11];
    const float* b2   = (const float*)d_in[12];
    float* out = (float*)d_out;

    k1_prep<<<BB, 256>>>(gaf, Wq, Wkv, Wout);
    for (int q = 0; q < NQ; q++) {
        k2_stats<<<dim3(8, 2, QB), 256>>>(tcf, q);
        k4_A<<<dim3(16, QB), 256>>>(tcf, q);
    }
    k5_head<<<BB, 256>>>(ln1g, ln1b, W1, b1, ln2g, ln2b, W2, b2, out);
}